// round 2
// baseline (speedup 1.0000x reference)
#include <cuda_runtime.h>
#include <math.h>

// Problem constants: B=2, S=2048, E=1024, H=16, HD=64
#define B_  2
#define S_  2048
#define E_  1024
#define H_  16
#define HD_ 64
#define M_  (B_*S_)     // 4096 tokens
#define FF_ (4*E_)      // 4096

// ---------------- scratch (static device globals; no allocation allowed) ---
__device__ float s_qkv [M_ * 3 * E_];   // 50.3 MB  [tok][3E] (q|k|v interleaved per token)
__device__ float s_attn[M_ * E_];       // 16.8 MB  attention output, token-major
__device__ float s_proj[M_ * E_];       // 16.8 MB  out-projection
__device__ float s_x1  [M_ * E_];       // 16.8 MB  LN1 output (also residual for LN2)
__device__ float s_ff1 [M_ * FF_];      // 67.1 MB  gelu(ff1)
__device__ float s_ff2 [M_ * E_];       // 16.8 MB  ff2 output

__device__ __forceinline__ float gelu_f(float v) {
    return 0.5f * v * (1.0f + erff(v * 0.70710678118654752f));
}

// ---------------------------------------------------------------------------
// GEMM: C[M,N] = A[M,K] @ B[K,N] + bias, optional exact GELU epilogue.
// 128x128 block tile, BK=16, 8x8 per thread (split 4+4), double-buffered smem.
// All dims are multiples of 128 (M=4096, N in {1024,3072,4096}, K in {1024,4096}).
// ---------------------------------------------------------------------------
template<int ACT>
__global__ void __launch_bounds__(256, 2) gemm_kernel(
    const float* __restrict__ A, const float* __restrict__ Bm,
    const float* __restrict__ bias, float* __restrict__ C,
    int M, int N, int K)
{
    __shared__ float As[2][16][129];   // transposed A tile, stride 129 kills STS conflicts
    __shared__ float Bs[2][16][128];

    const int tid = threadIdx.x;
    const int tx = tid & 15, ty = tid >> 4;
    const int bm = blockIdx.y << 7, bn = blockIdx.x << 7;

    const float* Ab = A + (size_t)bm * K;
    const float* Bb = Bm + bn;

    // global->smem load indices (2 float4 per thread per tile, each matrix)
    const int ar0 = tid >> 2;            // 0..63
    const int ak0 = (tid & 3) << 2;      // 0,4,8,12
    const int ar1 = ar0 + 64;
    const int bk0 = tid >> 5;            // 0..7
    const int bn0 = (tid & 31) << 2;     // 0..124
    const int bk1 = bk0 + 8;

    float acc[8][8];
    #pragma unroll
    for (int i = 0; i < 8; i++)
        #pragma unroll
        for (int j = 0; j < 8; j++) acc[i][j] = 0.f;

    // preload tile 0
    {
        float4 a0 = *(const float4*)(Ab + (size_t)ar0 * K + ak0);
        float4 a1 = *(const float4*)(Ab + (size_t)ar1 * K + ak0);
        float4 b0 = *(const float4*)(Bb + (size_t)bk0 * N + bn0);
        float4 b1 = *(const float4*)(Bb + (size_t)bk1 * N + bn0);
        As[0][ak0+0][ar0] = a0.x; As[0][ak0+1][ar0] = a0.y;
        As[0][ak0+2][ar0] = a0.z; As[0][ak0+3][ar0] = a0.w;
        As[0][ak0+0][ar1] = a1.x; As[0][ak0+1][ar1] = a1.y;
        As[0][ak0+2][ar1] = a1.z; As[0][ak0+3][ar1] = a1.w;
        *(float4*)(&Bs[0][bk0][bn0]) = b0;
        *(float4*)(&Bs[0][bk1][bn0]) = b1;
    }
    __syncthreads();

    const int tiles = K >> 4;
    for (int t = 0; t < tiles; ++t) {
        const int cur = t & 1;
        float4 pa0, pa1, pb0, pb1;
        if (t + 1 < tiles) {
            const int k0 = (t + 1) << 4;
            pa0 = *(const float4*)(Ab + (size_t)ar0 * K + k0 + ak0);
            pa1 = *(const float4*)(Ab + (size_t)ar1 * K + k0 + ak0);
            pb0 = *(const float4*)(Bb + (size_t)(k0 + bk0) * N + bn0);
            pb1 = *(const float4*)(Bb + (size_t)(k0 + bk1) * N + bn0);
        }
        #pragma unroll
        for (int kk = 0; kk < 16; kk++) {
            float a[8], b[8];
            #pragma unroll
            for (int i = 0; i < 4; i++) {
                a[i]   = As[cur][kk][(ty << 2) + i];
                a[4+i] = As[cur][kk][64 + (ty << 2) + i];
            }
            float4 bv0 = *(const float4*)(&Bs[cur][kk][tx << 2]);
            float4 bv1 = *(const float4*)(&Bs[cur][kk][64 + (tx << 2)]);
            b[0]=bv0.x; b[1]=bv0.y; b[2]=bv0.z; b[3]=bv0.w;
            b[4]=bv1.x; b[5]=bv1.y; b[6]=bv1.z; b[7]=bv1.w;
            #pragma unroll
            for (int i = 0; i < 8; i++)
                #pragma unroll
                for (int j = 0; j < 8; j++)
                    acc[i][j] = fmaf(a[i], b[j], acc[i][j]);
        }
        if (t + 1 < tiles) {
            const int nb = cur ^ 1;
            As[nb][ak0+0][ar0] = pa0.x; As[nb][ak0+1][ar0] = pa0.y;
            As[nb][ak0+2][ar0] = pa0.z; As[nb][ak0+3][ar0] = pa0.w;
            As[nb][ak0+0][ar1] = pa1.x; As[nb][ak0+1][ar1] = pa1.y;
            As[nb][ak0+2][ar1] = pa1.z; As[nb][ak0+3][ar1] = pa1.w;
            *(float4*)(&Bs[nb][bk0][bn0]) = pb0;
            *(float4*)(&Bs[nb][bk1][bn0]) = pb1;
            __syncthreads();
        }
    }

    // epilogue: bias (+ gelu), float4 stores
    #pragma unroll
    for (int i = 0; i < 8; i++) {
        const int r = bm + ((i < 4) ? (ty << 2) + i : 64 + (ty << 2) + i - 4);
        float* Crow = C + (size_t)r * N;
        #pragma unroll
        for (int jj = 0; jj < 2; jj++) {
            const int c0 = bn + jj * 64 + (tx << 2);
            float v0 = acc[i][jj*4+0] + bias[c0+0];
            float v1 = acc[i][jj*4+1] + bias[c0+1];
            float v2 = acc[i][jj*4+2] + bias[c0+2];
            float v3 = acc[i][jj*4+3] + bias[c0+3];
            if (ACT) { v0 = gelu_f(v0); v1 = gelu_f(v1); v2 = gelu_f(v2); v3 = gelu_f(v3); }
            *(float4*)(Crow + c0) = make_float4(v0, v1, v2, v3);
        }
    }
}

// ---------------------------------------------------------------------------
// Flash attention, fp32. One block = one (b,h) and a 64-row Q tile.
// Online softmax over 32 K/V tiles of 64. 16x16 threads, 4x4 outputs each.
// Reads q/k/v straight from the interleaved qkv buffer (no transpose pass).
// ---------------------------------------------------------------------------
__global__ void __launch_bounds__(256) flash_kernel(
    const float* __restrict__ qkv, float* __restrict__ attn)
{
    const int tid = threadIdx.x;
    const int tx = tid & 15, ty = tid >> 4;
    const int q0 = blockIdx.x << 6;
    const int b  = blockIdx.y >> 4, h = blockIdx.y & 15;

    extern __shared__ float sm[];
    float* Qs = sm;               // [64][64]
    float* Kt = Qs + 64 * 64;     // [64 d][68]  (d-major, stride 68: aligned + low conflicts)
    float* Vs = Kt + 64 * 68;     // [64][64]
    float* Ps = Vs + 64 * 64;     // [64][64]

    const float* qb = qkv + (size_t)b * S_ * (3 * E_) + (size_t)h * HD_;
    const float* kb = qb + E_;
    const float* vb = qb + 2 * E_;

    // load Q tile
    #pragma unroll
    for (int i = 0; i < 4; i++) {
        int lin = tid + (i << 8);
        int r = lin >> 4, d4 = (lin & 15) << 2;
        float4 v = *(const float4*)(qb + (size_t)(q0 + r) * (3 * E_) + d4);
        *(float4*)(Qs + (r << 6) + d4) = v;
    }

    float m_r[4], l_r[4], O[4][4];
    #pragma unroll
    for (int i = 0; i < 4; i++) {
        m_r[i] = -1e30f; l_r[i] = 0.f;
        #pragma unroll
        for (int j = 0; j < 4; j++) O[i][j] = 0.f;
    }

    for (int t = 0; t < S_ / 64; ++t) {
        __syncthreads();
        // load K (transposed to d-major) and V tiles
        #pragma unroll
        for (int i = 0; i < 4; i++) {
            int lin = tid + (i << 8);
            int r = lin >> 4, d4 = (lin & 15) << 2;
            size_t go = (size_t)(t * 64 + r) * (3 * E_) + d4;
            float4 kv = *(const float4*)(kb + go);
            Kt[(d4+0)*68 + r] = kv.x;
            Kt[(d4+1)*68 + r] = kv.y;
            Kt[(d4+2)*68 + r] = kv.z;
            Kt[(d4+3)*68 + r] = kv.w;
            float4 vv = *(const float4*)(vb + go);
            *(float4*)(Vs + (r << 6) + d4) = vv;
        }
        __syncthreads();

        // scores: s[i][j] = Q[row_i] . K[col_j]
        float s[4][4];
        #pragma unroll
        for (int i = 0; i < 4; i++)
            #pragma unroll
            for (int j = 0; j < 4; j++) s[i][j] = 0.f;
        for (int d = 0; d < 64; d++) {
            float4 kv4 = *(const float4*)(Kt + d * 68 + (tx << 2));
            float kc0 = kv4.x, kc1 = kv4.y, kc2 = kv4.z, kc3 = kv4.w;
            #pragma unroll
            for (int i = 0; i < 4; i++) {
                float qv = Qs[(((ty << 2) + i) << 6) + d];
                s[i][0] = fmaf(qv, kc0, s[i][0]);
                s[i][1] = fmaf(qv, kc1, s[i][1]);
                s[i][2] = fmaf(qv, kc2, s[i][2]);
                s[i][3] = fmaf(qv, kc3, s[i][3]);
            }
        }

        // online softmax (row groups = 16 lanes sharing ty)
        #pragma unroll
        for (int i = 0; i < 4; i++) {
            float mx = -1e30f;
            #pragma unroll
            for (int j = 0; j < 4; j++) { s[i][j] *= 0.125f; mx = fmaxf(mx, s[i][j]); }
            #pragma unroll
            for (int o = 8; o > 0; o >>= 1)
                mx = fmaxf(mx, __shfl_xor_sync(0xffffffffu, mx, o));
            float mnew  = fmaxf(m_r[i], mx);
            float alpha = __expf(m_r[i] - mnew);
            float p0 = __expf(s[i][0] - mnew);
            float p1 = __expf(s[i][1] - mnew);
            float p2 = __expf(s[i][2] - mnew);
            float p3 = __expf(s[i][3] - mnew);
            float rs = p0 + p1 + p2 + p3;
            #pragma unroll
            for (int o = 8; o > 0; o >>= 1)
                rs += __shfl_xor_sync(0xffffffffu, rs, o);
            l_r[i] = l_r[i] * alpha + rs;
            m_r[i] = mnew;
            #pragma unroll
            for (int j = 0; j < 4; j++) O[i][j] *= alpha;
            *(float4*)(Ps + (((ty << 2) + i) << 6) + (tx << 2)) = make_float4(p0, p1, p2, p3);
        }
        __syncthreads();

        // O += P @ V
        for (int k = 0; k < 64; k++) {
            float4 vv = *(const float4*)(Vs + (k << 6) + (tx << 2));
            #pragma unroll
            for (int i = 0; i < 4; i++) {
                float pr = Ps[(((ty << 2) + i) << 6) + k];
                O[i][0] = fmaf(pr, vv.x, O[i][0]);
                O[i][1] = fmaf(pr, vv.y, O[i][1]);
                O[i][2] = fmaf(pr, vv.z, O[i][2]);
                O[i][3] = fmaf(pr, vv.w, O[i][3]);
            }
        }
    }

    // normalize + write [B,S,E] token-major (heads concatenated)
    #pragma unroll
    for (int i = 0; i < 4; i++) {
        float inv = 1.f / l_r[i];
        int r = q0 + (ty << 2) + i;
        float4 o = make_float4(O[i][0]*inv, O[i][1]*inv, O[i][2]*inv, O[i][3]*inv);
        *(float4*)(attn + (size_t)(b * S_ + r) * E_ + h * HD_ + (tx << 2)) = o;
    }
}

// ---------------------------------------------------------------------------
// Fused residual-add + LayerNorm. One block per token, 256 threads x 4 elems.
// out = LN(a + bsrc) * g + be
// ---------------------------------------------------------------------------
__global__ void __launch_bounds__(256) ln_kernel(
    const float* __restrict__ a, const float* __restrict__ bsrc,
    const float* __restrict__ g, const float* __restrict__ be,
    float* __restrict__ out)
{
    const int tok = blockIdx.x;
    const int tid = threadIdx.x;
    const float* pa = a    + (size_t)tok * E_;
    const float* pb = bsrc + (size_t)tok * E_;

    float r[4]; float s = 0.f;
    #pragma unroll
    for (int i = 0; i < 4; i++) {
        int e = tid + (i << 8);
        r[i] = pa[e] + pb[e];
        s += r[i];
    }
    __shared__ float red[8];
    #pragma unroll
    for (int o = 16; o > 0; o >>= 1) s += __shfl_xor_sync(0xffffffffu, s, o);
    if ((tid & 31) == 0) red[tid >> 5] = s;
    __syncthreads();
    float tot = 0.f;
    #pragma unroll
    for (int w = 0; w < 8; w++) tot += red[w];
    const float mean = tot * (1.0f / E_);

    float vs = 0.f;
    #pragma unroll
    for (int i = 0; i < 4; i++) { float d = r[i] - mean; vs += d * d; }
    #pragma unroll
    for (int o = 16; o > 0; o >>= 1) vs += __shfl_xor_sync(0xffffffffu, vs, o);
    __syncthreads();
    if ((tid & 31) == 0) red[tid >> 5] = vs;
    __syncthreads();
    float vtot = 0.f;
    #pragma unroll
    for (int w = 0; w < 8; w++) vtot += red[w];
    const float rstd = rsqrtf(vtot * (1.0f / E_) + 1e-5f);

    #pragma unroll
    for (int i = 0; i < 4; i++) {
        int e = tid + (i << 8);
        out[(size_t)tok * E_ + e] = (r[i] - mean) * rstd * g[e] + be[e];
    }
}

// ---------------------------------------------------------------------------
extern "C" void kernel_launch(void* const* d_in, const int* in_sizes, int n_in,
                              void* d_out, int out_size)
{
    const float* x     = (const float*)d_in[0];
    const float* w_qkv = (const float*)d_in[1];
    const float* b_qkv = (const float*)d_in[2];
    const float* w_out = (const float*)d_in[3];
    const float* b_out = (const float*)d_in[4];
    const float* w_ff1 = (const float*)d_in[5];
    const float* b_ff1 = (const float*)d_in[6];
    const float* w_ff2 = (const float*)d_in[7];
    const float* b_ff2 = (const float*)d_in[8];
    const float* g1    = (const float*)d_in[9];
    const float* be1   = (const float*)d_in[10];
    const float* g2    = (const float*)d_in[11];
    const float* be2   = (const float*)d_in[12];
    float* out = (float*)d_out;

    float *p_qkv, *p_attn, *p_proj, *p_x1, *p_ff1, *p_ff2;
    cudaGetSymbolAddress((void**)&p_qkv,  s_qkv);
    cudaGetSymbolAddress((void**)&p_attn, s_attn);
    cudaGetSymbolAddress((void**)&p_proj, s_proj);
    cudaGetSymbolAddress((void**)&p_x1,   s_x1);
    cudaGetSymbolAddress((void**)&p_ff1,  s_ff1);
    cudaGetSymbolAddress((void**)&p_ff2,  s_ff2);

    // 1) QKV projection: [4096,1024] @ [1024,3072] + bias
    gemm_kernel<0><<<dim3(3 * E_ / 128, M_ / 128), 256>>>(
        x, w_qkv, b_qkv, p_qkv, M_, 3 * E_, E_);

    // 2) flash attention over interleaved qkv
    size_t shmem = (size_t)(64*64 + 64*68 + 64*64 + 64*64) * sizeof(float);  // 66560 B
    cudaFuncSetAttribute(flash_kernel,
                         cudaFuncAttributeMaxDynamicSharedMemorySize, (int)shmem);
    flash_kernel<<<dim3(S_ / 64, B_ * H_), 256, shmem>>>(p_qkv, p_attn);

    // 3) output projection
    gemm_kernel<0><<<dim3(E_ / 128, M_ / 128), 256>>>(
        p_attn, w_out, b_out, p_proj, M_, E_, E_);

    // 4) LN1( x + proj )
    ln_kernel<<<M_, 256>>>(x, p_proj, g1, be1, p_x1);

    // 5) FF1 + exact GELU
    gemm_kernel<1><<<dim3(FF_ / 128, M_ / 128), 256>>>(
        p_x1, w_ff1, b_ff1, p_ff1, M_, FF_, E_);

    // 6) FF2
    gemm_kernel<0><<<dim3(E_ / 128, M_ / 128), 256>>>(
        p_ff1, w_ff2, b_ff2, p_ff2, M_, E_, FF_);

    // 7) LN2( x1 + ff2 ) -> output
    ln_kernel<<<M_, 256>>>(p_x1, p_ff2, g2, be2, out);
}

// round 5
// speedup vs baseline: 1.7728x; 1.7728x over previous
#include <cuda_runtime.h>
#include <math.h>
#include <stdint.h>

// Problem constants: B=2, S=2048, E=1024, H=16, HD=64
#define B_  2
#define S_  2048
#define E_  1024
#define H_  16
#define HD_ 64
#define M_  (B_*S_)     // 4096 tokens
#define FF_ (4*E_)      // 4096

// ---------------- scratch (static device globals; no allocation allowed) ---
__device__ float s_qkv [M_ * 3 * E_];
__device__ float s_attn[M_ * E_];
__device__ float s_proj[M_ * E_];
__device__ float s_x1  [M_ * E_];
__device__ float s_ff1 [M_ * FF_];
__device__ float s_ff2 [M_ * E_];

__device__ __forceinline__ float gelu_f(float v) {
    return 0.5f * v * (1.0f + erff(v * 0.70710678118654752f));
}

__device__ __forceinline__ uint32_t smem_u32(const void* p) {
    uint32_t a;
    asm("{ .reg .u64 t; cvta.to.shared.u64 t, %1; cvt.u32.u64 %0, t; }"
        : "=r"(a) : "l"(p));
    return a;
}
__device__ __forceinline__ void cpa16(uint32_t s, const void* g) {
    asm volatile("cp.async.cg.shared.global [%0], [%1], 16;" :: "r"(s), "l"(g) : "memory");
}
#define CP_COMMIT() asm volatile("cp.async.commit_group;" ::: "memory")

__device__ __forceinline__ void ldsm4(uint32_t& r0, uint32_t& r1, uint32_t& r2,
                                      uint32_t& r3, uint32_t addr) {
    asm volatile("ldmatrix.sync.aligned.m8n8.x4.shared.b16 {%0,%1,%2,%3}, [%4];"
                 : "=r"(r0), "=r"(r1), "=r"(r2), "=r"(r3) : "r"(addr));
}
__device__ __forceinline__ void mma_tf32(float* d, const uint32_t* a, const float* b) {
    asm volatile(
        "mma.sync.aligned.m16n8k8.row.col.f32.tf32.tf32.f32 "
        "{%0,%1,%2,%3}, {%4,%5,%6,%7}, {%8,%9}, {%0,%1,%2,%3};"
        : "+f"(d[0]), "+f"(d[1]), "+f"(d[2]), "+f"(d[3])
        : "r"(a[0]), "r"(a[1]), "r"(a[2]), "r"(a[3]),
          "r"(__float_as_uint(b[0])), "r"(__float_as_uint(b[1])));
}

// ===========================================================================
// TF32 mma.sync GEMM: C[M,N] = A[M,K] @ B[K,N] + bias (+GELU).
// CTA 128x128, BK=32, double-buffered cp.async.
// SMEM per stage: A 128 rows x 36 floats (pad->conflict-free ldmatrix) = 18432B
//                 B 32 rows x 136 floats (pad->conflict-free LDS)      = 17408B
// 8 warps: 2(M) x 4(N); warp tile 64x32 via m16n8k8: 4 m-tiles x 4 n-tiles.
// ===========================================================================
#define GSTAGE 35840
#define GEMM_SMEM (2 * GSTAGE)

template<int ACT>
__global__ void __launch_bounds__(256, 2) gemm_mma(
    const float* __restrict__ A, const float* __restrict__ Bm,
    const float* __restrict__ bias, float* __restrict__ C,
    int M, int N, int K)
{
    extern __shared__ char smraw[];
    const uint32_t sbase = smem_u32(smraw);
    const int tid = threadIdx.x, lane = tid & 31, wid = tid >> 5;
    const int wm = wid & 1, wn = wid >> 1;           // warp: m64 x n32
    const int bm = blockIdx.y << 7, bn = blockIdx.x << 7;

    float acc[4][4][4];
    #pragma unroll
    for (int i = 0; i < 4; i++)
        #pragma unroll
        for (int j = 0; j < 4; j++)
            #pragma unroll
            for (int q = 0; q < 4; q++) acc[i][j][q] = 0.f;

    const float* Abase = A + (size_t)bm * K;
    const float* Bbase = Bm + bn;

    auto load_stage = [&](int kt, int s) {
        const uint32_t a0 = sbase + (uint32_t)s * GSTAGE;
        const uint32_t b0 = a0 + 18432u;
        const float* Ag = Abase + kt * 32;
        const float* Bg = Bbase + (size_t)(kt * 32) * N;
        #pragma unroll
        for (int i = 0; i < 4; i++) {
            int idx = tid + (i << 8);
            int r = idx >> 3, c = idx & 7;
            cpa16(a0 + (uint32_t)(r * 144 + c * 16), Ag + (size_t)r * K + c * 4);
        }
        #pragma unroll
        for (int i = 0; i < 4; i++) {
            int idx = tid + (i << 8);
            int k = idx >> 5, c = idx & 31;
            cpa16(b0 + (uint32_t)(k * 544 + c * 16), Bg + (size_t)k * N + c * 4);
        }
    };

    // ldmatrix lane map: lanes 0-7 -> rows 0-7 k0-3 (a0); 8-15 -> rows 8-15 (a1);
    // 16-23 -> rows 0-7 k4-7 (a2); 24-31 -> rows 8-15 k4-7 (a3).
    const uint32_t a_lane_off =
        (uint32_t)((wm * 64 + ((lane >> 3) & 1) * 8 + (lane & 7)) * 144
                   + ((lane >> 4) & 1) * 16);
    const int bk_row = lane & 3;          // k within 4
    const int bn_col = lane >> 2;         // n within 8

    const int T = K >> 5;
    load_stage(0, 0);
    CP_COMMIT();

    for (int t = 0; t < T; ++t) {
        if (t + 1 < T) { load_stage(t + 1, (t + 1) & 1); CP_COMMIT(); }
        if (t + 1 < T) asm volatile("cp.async.wait_group 1;" ::: "memory");
        else           asm volatile("cp.async.wait_group 0;" ::: "memory");
        __syncthreads();

        const int s = t & 1;
        const uint32_t aS = sbase + (uint32_t)s * GSTAGE + a_lane_off;
        const float* Bsp = (const float*)(smraw + s * GSTAGE + 18432);

        #pragma unroll
        for (int kk = 0; kk < 4; kk++) {
            uint32_t af[4][4];
            #pragma unroll
            for (int mt = 0; mt < 4; mt++)
                ldsm4(af[mt][0], af[mt][1], af[mt][2], af[mt][3],
                      aS + (uint32_t)(mt * 16 * 144 + kk * 32));
            float bf[4][2];
            const int k0 = kk * 8;
            #pragma unroll
            for (int nt = 0; nt < 4; nt++) {
                int n = wn * 32 + nt * 8 + bn_col;
                bf[nt][0] = Bsp[(k0 + bk_row) * 136 + n];
                bf[nt][1] = Bsp[(k0 + 4 + bk_row) * 136 + n];
            }
            #pragma unroll
            for (int mt = 0; mt < 4; mt++)
                #pragma unroll
                for (int nt = 0; nt < 4; nt++)
                    mma_tf32(acc[mt][nt], af[mt], bf[nt]);
        }
        __syncthreads();
    }

    // epilogue: bias (+gelu), float2 stores from accum fragments
    #pragma unroll
    for (int mt = 0; mt < 4; mt++) {
        #pragma unroll
        for (int half = 0; half < 2; half++) {
            const int r = bm + wm * 64 + mt * 16 + (lane >> 2) + half * 8;
            float* crow = C + (size_t)r * N;
            #pragma unroll
            for (int nt = 0; nt < 4; nt++) {
                const int c = bn + wn * 32 + nt * 8 + (lane & 3) * 2;
                float v0 = acc[mt][nt][half * 2 + 0] + bias[c];
                float v1 = acc[mt][nt][half * 2 + 1] + bias[c + 1];
                if (ACT) { v0 = gelu_f(v0); v1 = gelu_f(v1); }
                *(float2*)(crow + c) = make_float2(v0, v1);
            }
        }
    }
}

// ---------------------------------------------------------------------------
// Flash attention, fp32 (unchanged)
// ---------------------------------------------------------------------------
__global__ void __launch_bounds__(256) flash_kernel(
    const float* __restrict__ qkv, float* __restrict__ attn)
{
    const int tid = threadIdx.x;
    const int tx = tid & 15, ty = tid >> 4;
    const int q0 = blockIdx.x << 6;
    const int b  = blockIdx.y >> 4, h = blockIdx.y & 15;

    extern __shared__ float sm[];
    float* Qs = sm;
    float* Kt = Qs + 64 * 64;
    float* Vs = Kt + 64 * 68;
    float* Ps = Vs + 64 * 64;

    const float* qb = qkv + (size_t)b * S_ * (3 * E_) + (size_t)h * HD_;
    const float* kb = qb + E_;
    const float* vb = qb + 2 * E_;

    #pragma unroll
    for (int i = 0; i < 4; i++) {
        int lin = tid + (i << 8);
        int r = lin >> 4, d4 = (lin & 15) << 2;
        float4 v = *(const float4*)(qb + (size_t)(q0 + r) * (3 * E_) + d4);
        *(float4*)(Qs + (r << 6) + d4) = v;
    }

    float m_r[4], l_r[4], O[4][4];
    #pragma unroll
    for (int i = 0; i < 4; i++) {
        m_r[i] = -1e30f; l_r[i] = 0.f;
        #pragma unroll
        for (int j = 0; j < 4; j++) O[i][j] = 0.f;
    }

    for (int t = 0; t < S_ / 64; ++t) {
        __syncthreads();
        #pragma unroll
        for (int i = 0; i < 4; i++) {
            int lin = tid + (i << 8);
            int r = lin >> 4, d4 = (lin & 15) << 2;
            size_t go = (size_t)(t * 64 + r) * (3 * E_) + d4;
            float4 kv = *(const float4*)(kb + go);
            Kt[(d4+0)*68 + r] = kv.x;
            Kt[(d4+1)*68 + r] = kv.y;
            Kt[(d4+2)*68 + r] = kv.z;
            Kt[(d4+3)*68 + r] = kv.w;
            float4 vv = *(const float4*)(vb + go);
            *(float4*)(Vs + (r << 6) + d4) = vv;
        }
        __syncthreads();

        float s[4][4];
        #pragma unroll
        for (int i = 0; i < 4; i++)
            #pragma unroll
            for (int j = 0; j < 4; j++) s[i][j] = 0.f;
        for (int d = 0; d < 64; d++) {
            float4 kv4 = *(const float4*)(Kt + d * 68 + (tx << 2));
            #pragma unroll
            for (int i = 0; i < 4; i++) {
                float qv = Qs[(((ty << 2) + i) << 6) + d];
                s[i][0] = fmaf(qv, kv4.x, s[i][0]);
                s[i][1] = fmaf(qv, kv4.y, s[i][1]);
                s[i][2] = fmaf(qv, kv4.z, s[i][2]);
                s[i][3] = fmaf(qv, kv4.w, s[i][3]);
            }
        }

        #pragma unroll
        for (int i = 0; i < 4; i++) {
            float mx = -1e30f;
            #pragma unroll
            for (int j = 0; j < 4; j++) { s[i][j] *= 0.125f; mx = fmaxf(mx, s[i][j]); }
            #pragma unroll
            for (int o = 8; o > 0; o >>= 1)
                mx = fmaxf(mx, __shfl_xor_sync(0xffffffffu, mx, o));
            float mnew  = fmaxf(m_r[i], mx);
            float alpha = __expf(m_r[i] - mnew);
            float p0 = __expf(s[i][0] - mnew);
            float p1 = __expf(s[i][1] - mnew);
            float p2 = __expf(s[i][2] - mnew);
            float p3 = __expf(s[i][3] - mnew);
            float rs = p0 + p1 + p2 + p3;
            #pragma unroll
            for (int o = 8; o > 0; o >>= 1)
                rs += __shfl_xor_sync(0xffffffffu, rs, o);
            l_r[i] = l_r[i] * alpha + rs;
            m_r[i] = mnew;
            #pragma unroll
            for (int j = 0; j < 4; j++) O[i][j] *= alpha;
            *(float4*)(Ps + (((ty << 2) + i) << 6) + (tx << 2)) = make_float4(p0, p1, p2, p3);
        }
        __syncthreads();

        for (int k = 0; k < 64; k++) {
            float4 vv = *(const float4*)(Vs + (k << 6) + (tx << 2));
            #pragma unroll
            for (int i = 0; i < 4; i++) {
                float pr = Ps[(((ty << 2) + i) << 6) + k];
                O[i][0] = fmaf(pr, vv.x, O[i][0]);
                O[i][1] = fmaf(pr, vv.y, O[i][1]);
                O[i][2] = fmaf(pr, vv.z, O[i][2]);
                O[i][3] = fmaf(pr, vv.w, O[i][3]);
            }
        }
    }

    #pragma unroll
    for (int i = 0; i < 4; i++) {
        float inv = 1.f / l_r[i];
        int r = q0 + (ty << 2) + i;
        float4 o = make_float4(O[i][0]*inv, O[i][1]*inv, O[i][2]*inv, O[i][3]*inv);
        *(float4*)(attn + (size_t)(b * S_ + r) * E_ + h * HD_ + (tx << 2)) = o;
    }
}

// ---------------------------------------------------------------------------
// Fused residual-add + LayerNorm (unchanged)
// ---------------------------------------------------------------------------
__global__ void __launch_bounds__(256) ln_kernel(
    const float* __restrict__ a, const float* __restrict__ bsrc,
    const float* __restrict__ g, const float* __restrict__ be,
    float* __restrict__ out)
{
    const int tok = blockIdx.x;
    const int tid = threadIdx.x;
    const float* pa = a    + (size_t)tok * E_;
    const float* pb = bsrc + (size_t)tok * E_;

    float r[4]; float s = 0.f;
    #pragma unroll
    for (int i = 0; i < 4; i++) {
        int e = tid + (i << 8);
        r[i] = pa[e] + pb[e];
        s += r[i];
    }
    __shared__ float red[8];
    #pragma unroll
    for (int o = 16; o > 0; o >>= 1) s += __shfl_xor_sync(0xffffffffu, s, o);
    if ((tid & 31) == 0) red[tid >> 5] = s;
    __syncthreads();
    float tot = 0.f;
    #pragma unroll
    for (int w = 0; w < 8; w++) tot += red[w];
    const float mean = tot * (1.0f / E_);

    float vs = 0.f;
    #pragma unroll
    for (int i = 0; i < 4; i++) { float d = r[i] - mean; vs += d * d; }
    #pragma unroll
    for (int o = 16; o > 0; o >>= 1) vs += __shfl_xor_sync(0xffffffffu, vs, o);
    __syncthreads();
    if ((tid & 31) == 0) red[tid >> 5] = vs;
    __syncthreads();
    float vtot = 0.f;
    #pragma unroll
    for (int w = 0; w < 8; w++) vtot += red[w];
    const float rstd = rsqrtf(vtot * (1.0f / E_) + 1e-5f);

    #pragma unroll
    for (int i = 0; i < 4; i++) {
        int e = tid + (i << 8);
        out[(size_t)tok * E_ + e] = (r[i] - mean) * rstd * g[e] + be[e];
    }
}

// ---------------------------------------------------------------------------
extern "C" void kernel_launch(void* const* d_in, const int* in_sizes, int n_in,
                              void* d_out, int out_size)
{
    const float* x     = (const float*)d_in[0];
    const float* w_qkv = (const float*)d_in[1];
    const float* b_qkv = (const float*)d_in[2];
    const float* w_out = (const float*)d_in[3];
    const float* b_out = (const float*)d_in[4];
    const float* w_ff1 = (const float*)d_in[5];
    const float* b_ff1 = (const float*)d_in[6];
    const float* w_ff2 = (const float*)d_in[7];
    const float* b_ff2 = (const float*)d_in[8];
    const float* g1    = (const float*)d_in[9];
    const float* be1   = (const float*)d_in[10];
    const float* g2    = (const float*)d_in[11];
    const float* be2   = (const float*)d_in[12];
    float* out = (float*)d_out;

    float *p_qkv, *p_attn, *p_proj, *p_x1, *p_ff1, *p_ff2;
    cudaGetSymbolAddress((void**)&p_qkv,  s_qkv);
    cudaGetSymbolAddress((void**)&p_attn, s_attn);
    cudaGetSymbolAddress((void**)&p_proj, s_proj);
    cudaGetSymbolAddress((void**)&p_x1,   s_x1);
    cudaGetSymbolAddress((void**)&p_ff1,  s_ff1);
    cudaGetSymbolAddress((void**)&p_ff2,  s_ff2);

    cudaFuncSetAttribute(gemm_mma<0>, cudaFuncAttributeMaxDynamicSharedMemorySize, GEMM_SMEM);
    cudaFuncSetAttribute(gemm_mma<1>, cudaFuncAttributeMaxDynamicSharedMemorySize, GEMM_SMEM);

    // 1) QKV projection: [4096,1024] @ [1024,3072]
    gemm_mma<0><<<dim3(3 * E_ / 128, M_ / 128), 256, GEMM_SMEM>>>(
        x, w_qkv, b_qkv, p_qkv, M_, 3 * E_, E_);

    // 2) flash attention
    size_t shmem = (size_t)(64*64 + 64*68 + 64*64 + 64*64) * sizeof(float);
    cudaFuncSetAttribute(flash_kernel,
                         cudaFuncAttributeMaxDynamicSharedMemorySize, (int)shmem);
    flash_kernel<<<dim3(S_ / 64, B_ * H_), 256, shmem>>>(p_qkv, p_attn);

    // 3) output projection
    gemm_mma<0><<<dim3(E_ / 128, M_ / 128), 256, GEMM_SMEM>>>(
        p_attn, w_out, b_out, p_proj, M_, E_, E_);

    // 4) LN1( x + proj )
    ln_kernel<<<M_, 256>>>(x, p_proj, g1, be1, p_x1);

    // 5) FF1 + GELU
    gemm_mma<1><<<dim3(FF_ / 128, M_ / 128), 256, GEMM_SMEM>>>(
        p_x1, w_ff1, b_ff1, p_ff1, M_, FF_, E_);

    // 6) FF2
    gemm_mma<0><<<dim3(E_ / 128, M_ / 128), 256, GEMM_SMEM>>>(
        p_ff1, w_ff2, b_ff2, p_ff2, M_, E_, FF_);

    // 7) LN2( x1 + ff2 ) -> output
    ln_kernel<<<M_, 256>>>(p_x1, p_ff2, g2, be2, out);
}

// round 7
// speedup vs baseline: 2.8975x; 1.6344x over previous
#include <cuda_runtime.h>
#include <math.h>
#include <stdint.h>

// Problem constants: B=2, S=2048, E=1024, H=16, HD=64
#define B_  2
#define S_  2048
#define E_  1024
#define H_  16
#define HD_ 64
#define M_  (B_*S_)     // 4096 tokens
#define FF_ (4*E_)      // 4096

// ---------------- scratch (static device globals; no allocation allowed) ---
__device__ float s_qkv [M_ * 3 * E_];
__device__ float s_attn[M_ * E_];
__device__ float s_proj[M_ * E_];
__device__ float s_x1  [M_ * E_];
__device__ float s_ff1 [M_ * FF_];
__device__ float s_ff2 [M_ * E_];

__device__ __forceinline__ float gelu_f(float v) {
    return 0.5f * v * (1.0f + erff(v * 0.70710678118654752f));
}

__device__ __forceinline__ uint32_t smem_u32(const void* p) {
    uint32_t a;
    asm("{ .reg .u64 t; cvta.to.shared.u64 t, %1; cvt.u32.u64 %0, t; }"
        : "=r"(a) : "l"(p));
    return a;
}
__device__ __forceinline__ void cpa16(uint32_t s, const void* g) {
    asm volatile("cp.async.cg.shared.global [%0], [%1], 16;" :: "r"(s), "l"(g) : "memory");
}
#define CP_COMMIT() asm volatile("cp.async.commit_group;" ::: "memory")
#define CP_WAIT0()  asm volatile("cp.async.wait_group 0;" ::: "memory")

__device__ __forceinline__ void ldsm4(uint32_t& r0, uint32_t& r1, uint32_t& r2,
                                      uint32_t& r3, uint32_t addr) {
    asm volatile("ldmatrix.sync.aligned.m8n8.x4.shared.b16 {%0,%1,%2,%3}, [%4];"
                 : "=r"(r0), "=r"(r1), "=r"(r2), "=r"(r3) : "r"(addr));
}
__device__ __forceinline__ void mma_tf32(float* d, const uint32_t* a, const float* b) {
    asm volatile(
        "mma.sync.aligned.m16n8k8.row.col.f32.tf32.tf32.f32 "
        "{%0,%1,%2,%3}, {%4,%5,%6,%7}, {%8,%9}, {%0,%1,%2,%3};"
        : "+f"(d[0]), "+f"(d[1]), "+f"(d[2]), "+f"(d[3])
        : "r"(a[0]), "r"(a[1]), "r"(a[2]), "r"(a[3]),
          "r"(__float_as_uint(b[0])), "r"(__float_as_uint(b[1])));
}

// ===========================================================================
// TF32 mma.sync GEMM (single-sync double-buffered mainloop)
// ===========================================================================
#define GSTAGE 35840
#define GEMM_SMEM (2 * GSTAGE)

template<int ACT>
__global__ void __launch_bounds__(256, 2) gemm_mma(
    const float* __restrict__ A, const float* __restrict__ Bm,
    const float* __restrict__ bias, float* __restrict__ C,
    int M, int N, int K)
{
    extern __shared__ char smraw[];
    const uint32_t sbase = smem_u32(smraw);
    const int tid = threadIdx.x, lane = tid & 31, wid = tid >> 5;
    const int wm = wid & 1, wn = wid >> 1;           // warp: m64 x n32
    const int bm = blockIdx.y << 7, bn = blockIdx.x << 7;

    float acc[4][4][4];
    #pragma unroll
    for (int i = 0; i < 4; i++)
        #pragma unroll
        for (int j = 0; j < 4; j++)
            #pragma unroll
            for (int q = 0; q < 4; q++) acc[i][j][q] = 0.f;

    const float* Abase = A + (size_t)bm * K;
    const float* Bbase = Bm + bn;

    auto load_stage = [&](int kt, int s) {
        const uint32_t a0 = sbase + (uint32_t)s * GSTAGE;
        const uint32_t b0 = a0 + 18432u;
        const float* Ag = Abase + kt * 32;
        const float* Bg = Bbase + (size_t)(kt * 32) * N;
        #pragma unroll
        for (int i = 0; i < 4; i++) {
            int idx = tid + (i << 8);
            int r = idx >> 3, c = idx & 7;
            cpa16(a0 + (uint32_t)(r * 144 + c * 16), Ag + (size_t)r * K + c * 4);
        }
        #pragma unroll
        for (int i = 0; i < 4; i++) {
            int idx = tid + (i << 8);
            int k = idx >> 5, c = idx & 31;
            cpa16(b0 + (uint32_t)(k * 544 + c * 16), Bg + (size_t)k * N + c * 4);
        }
    };

    const uint32_t a_lane_off =
        (uint32_t)((wm * 64 + ((lane >> 3) & 1) * 8 + (lane & 7)) * 144
                   + ((lane >> 4) & 1) * 16);
    const int bk_row = lane & 3;
    const int bn_col = lane >> 2;

    const int T = K >> 5;
    load_stage(0, 0);
    CP_COMMIT();

    for (int t = 0; t < T; ++t) {
        CP_WAIT0();
        __syncthreads();     // tile t ready AND all warps done with the other buffer
        if (t + 1 < T) { load_stage(t + 1, (t + 1) & 1); CP_COMMIT(); }

        const int s = t & 1;
        const uint32_t aS = sbase + (uint32_t)s * GSTAGE + a_lane_off;
        const float* Bsp = (const float*)(smraw + s * GSTAGE + 18432);

        #pragma unroll
        for (int kk = 0; kk < 4; kk++) {
            uint32_t af[4][4];
            #pragma unroll
            for (int mt = 0; mt < 4; mt++)
                ldsm4(af[mt][0], af[mt][1], af[mt][2], af[mt][3],
                      aS + (uint32_t)(mt * 16 * 144 + kk * 32));
            float bf[4][2];
            const int k0 = kk * 8;
            #pragma unroll
            for (int nt = 0; nt < 4; nt++) {
                int n = wn * 32 + nt * 8 + bn_col;
                bf[nt][0] = Bsp[(k0 + bk_row) * 136 + n];
                bf[nt][1] = Bsp[(k0 + 4 + bk_row) * 136 + n];
            }
            #pragma unroll
            for (int mt = 0; mt < 4; mt++)
                #pragma unroll
                for (int nt = 0; nt < 4; nt++)
                    mma_tf32(acc[mt][nt], af[mt], bf[nt]);
        }
    }

    // epilogue: bias (+gelu)
    #pragma unroll
    for (int mt = 0; mt < 4; mt++) {
        #pragma unroll
        for (int half = 0; half < 2; half++) {
            const int r = bm + wm * 64 + mt * 16 + (lane >> 2) + half * 8;
            float* crow = C + (size_t)r * N;
            #pragma unroll
            for (int nt = 0; nt < 4; nt++) {
                const int c = bn + wn * 32 + nt * 8 + (lane & 3) * 2;
                float v0 = acc[mt][nt][half * 2 + 0] + bias[c];
                float v1 = acc[mt][nt][half * 2 + 1] + bias[c + 1];
                if (ACT) { v0 = gelu_f(v0); v1 = gelu_f(v1); }
                *(float2*)(crow + c) = make_float2(v0, v1);
            }
        }
    }
}

// ===========================================================================
// Flash attention on tf32 mma.sync.
// CTA: one (b,h), 64 Q rows. 8 warps = 2(M:32) x 4(N:16). K/V double-buffered.
// Strides: Q/K/P = 68 floats (ldmatrix + B-frag conflict-free), V = 72.
// ===========================================================================
#define FK 68
#define FV 72
#define FLASH_SMEM ((64*FK + 2*64*FK + 2*64*FV + 64*FK + 192) * 4)

__global__ void __launch_bounds__(256, 1) flash_mma(
    const float* __restrict__ qkv, float* __restrict__ attn)
{
    extern __shared__ float sm[];
    float* Qs = sm;                     // [64][68]
    float* Ks = Qs + 64 * FK;           // [2][64][68]
    float* Vs = Ks + 2 * 64 * FK;       // [2][64][72]
    float* Ps = Vs + 2 * 64 * FV;       // [64][68]
    float* mrow = Ps + 64 * FK;         // [64]
    float* lrow = mrow + 64;            // [64]
    float* arow = lrow + 64;            // [64]

    const int tid = threadIdx.x, lane = tid & 31, wid = tid >> 5;
    const int wm = wid & 1, wn = wid >> 1;
    const int q0 = blockIdx.x << 6;
    const int b  = blockIdx.y >> 4, h = blockIdx.y & 15;

    const float* qb = qkv + (size_t)b * S_ * (3 * E_) + h * HD_;
    const float* kb = qb + E_;
    const float* vb = qb + 2 * E_;

    // Q tile -> smem (once)
    #pragma unroll
    for (int i = 0; i < 4; i++) {
        int idx = tid + (i << 8);
        int r = idx >> 4, c = (idx & 15) << 2;
        float4 v = *(const float4*)(qb + (size_t)(q0 + r) * (3 * E_) + c);
        Qs[r*FK+c] = v.x; Qs[r*FK+c+1] = v.y; Qs[r*FK+c+2] = v.z; Qs[r*FK+c+3] = v.w;
    }
    if (tid < 64) { mrow[tid] = -1e30f; lrow[tid] = 0.f; }

    const uint32_t QsU = smem_u32(Qs), KsU = smem_u32(Ks),
                   VsU = smem_u32(Vs), PsU = smem_u32(Ps);

    auto load_kv = [&](int t, int s) {
        const float* kg = kb + (size_t)(t * 64) * (3 * E_);
        const float* vg = vb + (size_t)(t * 64) * (3 * E_);
        #pragma unroll
        for (int i = 0; i < 4; i++) {
            int idx = tid + (i << 8);
            int r = idx >> 4, c = (idx & 15) << 2;
            cpa16(KsU + (uint32_t)((s * 64 * FK + r * FK + c) * 4), kg + (size_t)r * (3 * E_) + c);
            cpa16(VsU + (uint32_t)((s * 64 * FV + r * FV + c) * 4), vg + (size_t)r * (3 * E_) + c);
        }
    };

    load_kv(0, 0);
    CP_COMMIT();

    // ldmatrix lane offset (bytes), stride FK floats (272B = odd*16B: conflict-free)
    const uint32_t a_lane = (uint32_t)(((((lane >> 3) & 1) * 8 + (lane & 7)) * FK
                                        + ((lane >> 4) & 1) * 4) * 4);
    const int rh = lane >> 2;        // 0..7
    const int c2 = (lane & 3) * 2;

    float O[2][2][4];
    #pragma unroll
    for (int a = 0; a < 2; a++)
        #pragma unroll
        for (int bb = 0; bb < 2; bb++)
            #pragma unroll
            for (int q = 0; q < 4; q++) O[a][bb][q] = 0.f;

    for (int t = 0; t < S_ / 64; ++t) {
        const int s = t & 1;
        CP_WAIT0();
        __syncthreads();                          // K/V[t] ready; prev reads of s^1 done
        if (t + 1 < S_ / 64) { load_kv(t + 1, s ^ 1); CP_COMMIT(); }

        // ---- S = Q K^T (tf32 mma) ----
        float sf[2][2][4];
        #pragma unroll
        for (int a = 0; a < 2; a++)
            #pragma unroll
            for (int bb = 0; bb < 2; bb++)
                #pragma unroll
                for (int q = 0; q < 4; q++) sf[a][bb][q] = 0.f;

        #pragma unroll
        for (int kk = 0; kk < 8; kk++) {
            uint32_t af[2][4];
            #pragma unroll
            for (int mt = 0; mt < 2; mt++)
                ldsm4(af[mt][0], af[mt][1], af[mt][2], af[mt][3],
                      QsU + (uint32_t)((wm * 32 + mt * 16) * FK * 4) + a_lane + kk * 32);
            float bfr[2][2];
            #pragma unroll
            for (int nt = 0; nt < 2; nt++) {
                int n = wn * 16 + nt * 8 + rh;
                bfr[nt][0] = Ks[s * 64 * FK + n * FK + kk * 8 + (lane & 3)];
                bfr[nt][1] = Ks[s * 64 * FK + n * FK + kk * 8 + 4 + (lane & 3)];
            }
            #pragma unroll
            for (int mt = 0; mt < 2; mt++)
                #pragma unroll
                for (int nt = 0; nt < 2; nt++)
                    mma_tf32(sf[mt][nt], af[mt], bfr[nt]);
        }
        // write scaled S to Ps
        #pragma unroll
        for (int mt = 0; mt < 2; mt++)
            #pragma unroll
            for (int nt = 0; nt < 2; nt++) {
                int row0 = wm * 32 + mt * 16 + rh;
                int col  = wn * 16 + nt * 8 + c2;
                *(float2*)&Ps[row0 * FK + col] =
                    make_float2(sf[mt][nt][0] * 0.125f, sf[mt][nt][1] * 0.125f);
                *(float2*)&Ps[(row0 + 8) * FK + col] =
                    make_float2(sf[mt][nt][2] * 0.125f, sf[mt][nt][3] * 0.125f);
            }
        __syncthreads();

        // ---- online softmax: 4 threads per row ----
        {
            int row = tid >> 2;
            float* pr = Ps + row * FK + (tid & 3) * 16;
            float4 v0 = *(float4*)(pr),     v1 = *(float4*)(pr + 4),
                   v2 = *(float4*)(pr + 8), v3 = *(float4*)(pr + 12);
            float mx = fmaxf(fmaxf(fmaxf(v0.x, v0.y), fmaxf(v0.z, v0.w)),
                             fmaxf(fmaxf(v1.x, v1.y), fmaxf(v1.z, v1.w)));
            mx = fmaxf(mx, fmaxf(fmaxf(fmaxf(v2.x, v2.y), fmaxf(v2.z, v2.w)),
                                 fmaxf(fmaxf(v3.x, v3.y), fmaxf(v3.z, v3.w))));
            mx = fmaxf(mx, __shfl_xor_sync(0xffffffffu, mx, 1));
            mx = fmaxf(mx, __shfl_xor_sync(0xffffffffu, mx, 2));
            float mo = mrow[row];
            float mn = fmaxf(mo, mx);
            v0.x = __expf(v0.x - mn); v0.y = __expf(v0.y - mn);
            v0.z = __expf(v0.z - mn); v0.w = __expf(v0.w - mn);
            v1.x = __expf(v1.x - mn); v1.y = __expf(v1.y - mn);
            v1.z = __expf(v1.z - mn); v1.w = __expf(v1.w - mn);
            v2.x = __expf(v2.x - mn); v2.y = __expf(v2.y - mn);
            v2.z = __expf(v2.z - mn); v2.w = __expf(v2.w - mn);
            v3.x = __expf(v3.x - mn); v3.y = __expf(v3.y - mn);
            v3.z = __expf(v3.z - mn); v3.w = __expf(v3.w - mn);
            *(float4*)(pr)      = v0; *(float4*)(pr + 4)  = v1;
            *(float4*)(pr + 8)  = v2; *(float4*)(pr + 12) = v3;
            float su = v0.x + v0.y + v0.z + v0.w + v1.x + v1.y + v1.z + v1.w
                     + v2.x + v2.y + v2.z + v2.w + v3.x + v3.y + v3.z + v3.w;
            su += __shfl_xor_sync(0xffffffffu, su, 1);
            su += __shfl_xor_sync(0xffffffffu, su, 2);
            if ((tid & 3) == 0) {
                float al = __expf(mo - mn);
                arow[row] = al;
                lrow[row] = lrow[row] * al + su;
                mrow[row] = mn;
            }
        }
        __syncthreads();

        // ---- rescale O, then O += P @ V ----
        #pragma unroll
        for (int mt = 0; mt < 2; mt++) {
            float a0 = arow[wm * 32 + mt * 16 + rh];
            float a1 = arow[wm * 32 + mt * 16 + 8 + rh];
            #pragma unroll
            for (int nt = 0; nt < 2; nt++) {
                O[mt][nt][0] *= a0; O[mt][nt][1] *= a0;
                O[mt][nt][2] *= a1; O[mt][nt][3] *= a1;
            }
        }
        #pragma unroll
        for (int kk = 0; kk < 8; kk++) {
            uint32_t af[2][4];
            #pragma unroll
            for (int mt = 0; mt < 2; mt++)
                ldsm4(af[mt][0], af[mt][1], af[mt][2], af[mt][3],
                      PsU + (uint32_t)((wm * 32 + mt * 16) * FK * 4) + a_lane + kk * 32);
            float bfr[2][2];
            #pragma unroll
            for (int nt = 0; nt < 2; nt++) {
                int n = wn * 16 + nt * 8 + rh;                       // d-dim
                bfr[nt][0] = Vs[s * 64 * FV + (kk * 8 + (lane & 3)) * FV + n];
                bfr[nt][1] = Vs[s * 64 * FV + (kk * 8 + 4 + (lane & 3)) * FV + n];
            }
            #pragma unroll
            for (int mt = 0; mt < 2; mt++)
                #pragma unroll
                for (int nt = 0; nt < 2; nt++)
                    mma_tf32(O[mt][nt], af[mt], bfr[nt]);
        }
    }

    // ---- normalize + write ----
    #pragma unroll
    for (int mt = 0; mt < 2; mt++) {
        int row0 = wm * 32 + mt * 16 + rh;
        float inv0 = 1.f / lrow[row0];
        float inv1 = 1.f / lrow[row0 + 8];
        #pragma unroll
        for (int nt = 0; nt < 2; nt++) {
            int col = h * HD_ + wn * 16 + nt * 8 + c2;
            *(float2*)&attn[(size_t)(b * S_ + q0 + row0) * E_ + col] =
                make_float2(O[mt][nt][0] * inv0, O[mt][nt][1] * inv0);
            *(float2*)&attn[(size_t)(b * S_ + q0 + row0 + 8) * E_ + col] =
                make_float2(O[mt][nt][2] * inv1, O[mt][nt][3] * inv1);
        }
    }
}

// ---------------------------------------------------------------------------
// Fused residual-add + LayerNorm (unchanged)
// ---------------------------------------------------------------------------
__global__ void __launch_bounds__(256) ln_kernel(
    const float* __restrict__ a, const float* __restrict__ bsrc,
    const float* __restrict__ g, const float* __restrict__ be,
    float* __restrict__ out)
{
    const int tok = blockIdx.x;
    const int tid = threadIdx.x;
    const float* pa = a    + (size_t)tok * E_;
    const float* pb = bsrc + (size_t)tok * E_;

    float r[4]; float s = 0.f;
    #pragma unroll
    for (int i = 0; i < 4; i++) {
        int e = tid + (i << 8);
        r[i] = pa[e] + pb[e];
        s += r[i];
    }
    __shared__ float red[8];
    #pragma unroll
    for (int o = 16; o > 0; o >>= 1) s += __shfl_xor_sync(0xffffffffu, s, o);
    if ((tid & 31) == 0) red[tid >> 5] = s;
    __syncthreads();
    float tot = 0.f;
    #pragma unroll
    for (int w = 0; w < 8; w++) tot += red[w];
    const float mean = tot * (1.0f / E_);

    float vs = 0.f;
    #pragma unroll
    for (int i = 0; i < 4; i++) { float d = r[i] - mean; vs += d * d; }
    #pragma unroll
    for (int o = 16; o > 0; o >>= 1) vs += __shfl_xor_sync(0xffffffffu, vs, o);
    __syncthreads();
    if ((tid & 31) == 0) red[tid >> 5] = vs;
    __syncthreads();
    float vtot = 0.f;
    #pragma unroll
    for (int w = 0; w < 8; w++) vtot += red[w];
    const float rstd = rsqrtf(vtot * (1.0f / E_) + 1e-5f);

    #pragma unroll
    for (int i = 0; i < 4; i++) {
        int e = tid + (i << 8);
        out[(size_t)tok * E_ + e] = (r[i] - mean) * rstd * g[e] + be[e];
    }
}

// ---------------------------------------------------------------------------
extern "C" void kernel_launch(void* const* d_in, const int* in_sizes, int n_in,
                              void* d_out, int out_size)
{
    const float* x     = (const float*)d_in[0];
    const float* w_qkv = (const float*)d_in[1];
    const float* b_qkv = (const float*)d_in[2];
    const float* w_out = (const float*)d_in[3];
    const float* b_out = (const float*)d_in[4];
    const float* w_ff1 = (const float*)d_in[5];
    const float* b_ff1 = (const float*)d_in[6];
    const float* w_ff2 = (const float*)d_in[7];
    const float* b_ff2 = (const float*)d_in[8];
    const float* g1    = (const float*)d_in[9];
    const float* be1   = (const float*)d_in[10];
    const float* g2    = (const float*)d_in[11];
    const float* be2   = (const float*)d_in[12];
    float* out = (float*)d_out;

    float *p_qkv, *p_attn, *p_proj, *p_x1, *p_ff1, *p_ff2;
    cudaGetSymbolAddress((void**)&p_qkv,  s_qkv);
    cudaGetSymbolAddress((void**)&p_attn, s_attn);
    cudaGetSymbolAddress((void**)&p_proj, s_proj);
    cudaGetSymbolAddress((void**)&p_x1,   s_x1);
    cudaGetSymbolAddress((void**)&p_ff1,  s_ff1);
    cudaGetSymbolAddress((void**)&p_ff2,  s_ff2);

    cudaFuncSetAttribute(gemm_mma<0>, cudaFuncAttributeMaxDynamicSharedMemorySize, GEMM_SMEM);
    cudaFuncSetAttribute(gemm_mma<1>, cudaFuncAttributeMaxDynamicSharedMemorySize, GEMM_SMEM);
    cudaFuncSetAttribute(flash_mma,   cudaFuncAttributeMaxDynamicSharedMemorySize, FLASH_SMEM);

    // 1) QKV projection
    gemm_mma<0><<<dim3(3 * E_ / 128, M_ / 128), 256, GEMM_SMEM>>>(
        x, w_qkv, b_qkv, p_qkv, M_, 3 * E_, E_);

    // 2) flash attention (tf32 mma)
    flash_mma<<<dim3(S_ / 64, B_ * H_), 256, FLASH_SMEM>>>(p_qkv, p_attn);

    // 3) output projection
    gemm_mma<0><<<dim3(E_ / 128, M_ / 128), 256, GEMM_SMEM>>>(
        p_attn, w_out, b_out, p_proj, M_, E_, E_);

    // 4) LN1( x + proj )
    ln_kernel<<<M_, 256>>>(x, p_proj, g1, be1, p_x1);

    // 5) FF1 + GELU
    gemm_mma<1><<<dim3(FF_ / 128, M_ / 128), 256, GEMM_SMEM>>>(
        p_x1, w_ff1, b_ff1, p_ff1, M_, FF_, E_);

    // 6) FF2
    gemm_mma<0><<<dim3(E_ / 128, M_ / 128), 256, GEMM_SMEM>>>(
        p_ff1, w_ff2, b_ff2, p_ff2, M_, E_, FF_);

    // 7) LN2( x1 + ff2 ) -> output
    ln_kernel<<<M_, 256>>>(p_x1, p_ff2, g2, be2, out);
}

// round 9
// speedup vs baseline: 4.6618x; 1.6089x over previous
#include <cuda_runtime.h>
#include <cuda_fp16.h>
#include <math.h>
#include <stdint.h>

// Problem constants: B=2, S=2048, E=1024, H=16, HD=64
#define B_  2
#define S_  2048
#define E_  1024
#define H_  16
#define HD_ 64
#define M_  (B_*S_)     // 4096 tokens
#define FF_ (4*E_)      // 4096

// ---------------- scratch (static device globals) --------------------------
__device__ __half h_x   [M_ * E_];
__device__ __half h_wqkv[E_ * 3 * E_];
__device__ __half h_wout[E_ * E_];
__device__ __half h_wff1[E_ * FF_];
__device__ __half h_wff2[FF_ * E_];
__device__ __half h_qkv [M_ * 3 * E_];
__device__ __half h_attn[M_ * E_];
__device__ __half h_x1  [M_ * E_];
__device__ __half h_ff1 [M_ * FF_];
__device__ float  s_proj[M_ * E_];
__device__ float  s_x1f [M_ * E_];
__device__ float  s_ff2 [M_ * E_];

__device__ __forceinline__ float gelu_f(float v) {
    return 0.5f * v * (1.0f + erff(v * 0.70710678118654752f));
}
__device__ __forceinline__ uint32_t smem_u32(const void* p) {
    uint32_t a;
    asm("{ .reg .u64 t; cvta.to.shared.u64 t, %1; cvt.u32.u64 %0, t; }"
        : "=r"(a) : "l"(p));
    return a;
}
__device__ __forceinline__ void cpa16(uint32_t s, const void* g) {
    asm volatile("cp.async.cg.shared.global [%0], [%1], 16;" :: "r"(s), "l"(g) : "memory");
}
#define CP_COMMIT() asm volatile("cp.async.commit_group;" ::: "memory")
#define CP_WAIT0()  asm volatile("cp.async.wait_group 0;" ::: "memory")

__device__ __forceinline__ void ldsm4(uint32_t& r0, uint32_t& r1, uint32_t& r2,
                                      uint32_t& r3, uint32_t addr) {
    asm volatile("ldmatrix.sync.aligned.m8n8.x4.shared.b16 {%0,%1,%2,%3}, [%4];"
                 : "=r"(r0), "=r"(r1), "=r"(r2), "=r"(r3) : "r"(addr));
}
__device__ __forceinline__ void ldsm4t(uint32_t& r0, uint32_t& r1, uint32_t& r2,
                                       uint32_t& r3, uint32_t addr) {
    asm volatile("ldmatrix.sync.aligned.m8n8.x4.trans.shared.b16 {%0,%1,%2,%3}, [%4];"
                 : "=r"(r0), "=r"(r1), "=r"(r2), "=r"(r3) : "r"(addr));
}
__device__ __forceinline__ void mma_f16(float* d, const uint32_t* a, const uint32_t* b) {
    asm volatile(
        "mma.sync.aligned.m16n8k16.row.col.f32.f16.f16.f32 "
        "{%0,%1,%2,%3}, {%4,%5,%6,%7}, {%8,%9}, {%0,%1,%2,%3};"
        : "+f"(d[0]), "+f"(d[1]), "+f"(d[2]), "+f"(d[3])
        : "r"(a[0]), "r"(a[1]), "r"(a[2]), "r"(a[3]), "r"(b[0]), "r"(b[1]));
}

// ---------------------------------------------------------------------------
// fp32 -> fp16 conversion (exact grids)
// ---------------------------------------------------------------------------
__global__ void conv_h(const float4* __restrict__ src, __half2* __restrict__ dst) {
    int i = blockIdx.x * blockDim.x + threadIdx.x;
    float4 v = src[i];
    dst[2*i]   = __floats2half2_rn(v.x, v.y);
    dst[2*i+1] = __floats2half2_rn(v.z, v.w);
}

// ===========================================================================
// FP16 mma.sync GEMM: C[M,N] = A[M,K] @ B[K,N] + bias (+GELU).
// CTA 128x128, BK=32, double-buffered. m16n8k16, warp 64x32 (2x4 warps).
// A stage: 128 rows x 40 halves (80B stride). B: 32 rows x 136 halves (272B).
// ===========================================================================
#define GA_BYTES (128 * 80)          // 10240
#define GB_BYTES (32 * 272)          // 8704
#define GSTG (GA_BYTES + GB_BYTES)   // 18944
#define GEMM_SMEM (2 * GSTG)

template<int ACT, int OUTH>
__global__ void __launch_bounds__(256, 2) gemm_h(
    const __half* __restrict__ A, const __half* __restrict__ Bm,
    const float* __restrict__ bias, void* __restrict__ Cv,
    int M, int N, int K)
{
    extern __shared__ char smraw[];
    const uint32_t sbase = smem_u32(smraw);
    const int tid = threadIdx.x, lane = tid & 31, wid = tid >> 5;
    const int wm = wid & 1, wn = wid >> 1;
    const int bm = blockIdx.y << 7, bn = blockIdx.x << 7;

    float acc[4][4][4];
    #pragma unroll
    for (int i = 0; i < 4; i++)
        #pragma unroll
        for (int j = 0; j < 4; j++)
            #pragma unroll
            for (int q = 0; q < 4; q++) acc[i][j][q] = 0.f;

    const __half* Abase = A + (size_t)bm * K;
    const __half* Bbase = Bm + bn;

    auto load_stage = [&](int kt, int s) {
        const uint32_t a0 = sbase + (uint32_t)s * GSTG;
        const uint32_t b0 = a0 + GA_BYTES;
        const __half* Ag = Abase + kt * 32;
        const __half* Bg = Bbase + (size_t)(kt * 32) * N;
        #pragma unroll
        for (int i = 0; i < 2; i++) {
            int idx = tid + (i << 8);
            int r = idx >> 2, c = idx & 3;
            cpa16(a0 + (uint32_t)(r * 80 + c * 16), Ag + (size_t)r * K + c * 8);
        }
        #pragma unroll
        for (int i = 0; i < 2; i++) {
            int idx = tid + (i << 8);
            int r = idx >> 4, c = idx & 15;
            cpa16(b0 + (uint32_t)(r * 272 + c * 16), Bg + (size_t)r * N + c * 8);
        }
    };

    // A ldmatrix.x4: lane -> row (lane&15), 16B chunk (lane>>4)
    const uint32_t a_lane = (uint32_t)((wm * 64 + (lane & 15)) * 80 + (lane >> 4) * 16);
    // B ldmatrix.x4.trans lane map (per 16-n pair)
    const int bK = ((lane >> 3) & 1) * 8 + (lane & 7);  // k row within 16
    const int bN = ((lane >> 4) & 1) * 8;               // n offset within 16

    const int T = K >> 5;
    load_stage(0, 0);
    CP_COMMIT();

    for (int t = 0; t < T; ++t) {
        CP_WAIT0();
        __syncthreads();
        if (t + 1 < T) { load_stage(t + 1, (t + 1) & 1); CP_COMMIT(); }

        const int s = t & 1;
        const uint32_t aS = sbase + (uint32_t)s * GSTG + a_lane;
        const uint32_t bS = sbase + (uint32_t)s * GSTG + GA_BYTES;

        #pragma unroll
        for (int kk = 0; kk < 2; kk++) {
            uint32_t af[4][4];
            #pragma unroll
            for (int mt = 0; mt < 4; mt++)
                ldsm4(af[mt][0], af[mt][1], af[mt][2], af[mt][3],
                      aS + (uint32_t)(mt * 16 * 80 + kk * 32));
            uint32_t bf[4][2];
            #pragma unroll
            for (int ntp = 0; ntp < 2; ntp++) {
                uint32_t r0, r1, r2, r3;
                uint32_t baddr = bS + (uint32_t)((kk * 16 + bK) * 272
                                + (wn * 32 + ntp * 16 + bN) * 2);
                ldsm4t(r0, r1, r2, r3, baddr);
                bf[2*ntp][0] = r0; bf[2*ntp][1] = r1;
                bf[2*ntp+1][0] = r2; bf[2*ntp+1][1] = r3;
            }
            #pragma unroll
            for (int mt = 0; mt < 4; mt++)
                #pragma unroll
                for (int nt = 0; nt < 4; nt++)
                    mma_f16(acc[mt][nt], af[mt], bf[nt]);
        }
    }

    // epilogue: bias (+gelu), fp16 or fp32 out
    #pragma unroll
    for (int mt = 0; mt < 4; mt++) {
        #pragma unroll
        for (int half = 0; half < 2; half++) {
            const int r = bm + wm * 64 + mt * 16 + (lane >> 2) + half * 8;
            #pragma unroll
            for (int nt = 0; nt < 4; nt++) {
                const int c = bn + wn * 32 + nt * 8 + (lane & 3) * 2;
                float v0 = acc[mt][nt][half * 2 + 0] + bias[c];
                float v1 = acc[mt][nt][half * 2 + 1] + bias[c + 1];
                if (ACT) { v0 = gelu_f(v0); v1 = gelu_f(v1); }
                if (OUTH) {
                    __half* C = (__half*)Cv;
                    *(__half2*)(C + (size_t)r * N + c) = __floats2half2_rn(v0, v1);
                } else {
                    float* C = (float*)Cv;
                    *(float2*)(C + (size_t)r * N + c) = make_float2(v0, v1);
                }
            }
        }
    }
}

// ===========================================================================
// Flash attention, fp16 mma. CTA: one (b,h), 64 Q rows, 8 warps 2(M)x4(N).
// Q/K/V/P fp16 stride 72 halves (144B); scores fp32 stride 68 floats.
// ===========================================================================
#define OFF_Q  0
#define OFF_K  9216
#define OFF_V  (9216 + 18432)
#define OFF_SF (9216 + 18432 + 18432)
#define OFF_PH (OFF_SF + 17408)
#define OFF_RW (OFF_PH + 9216)
#define FLASH_SMEM (OFF_RW + 768)

__global__ void __launch_bounds__(256, 2) flash_h(
    const __half* __restrict__ qkv, __half* __restrict__ attn)
{
    extern __shared__ char smraw[];
    const uint32_t base = smem_u32(smraw);
    const uint32_t QsU = base + OFF_Q, KsU = base + OFF_K, VsU = base + OFF_V;
    __half* Ph  = (__half*)(smraw + OFF_PH);
    float* Sf   = (float*)(smraw + OFF_SF);
    float* mrow = (float*)(smraw + OFF_RW);
    float* lrow = mrow + 64;
    float* arow = lrow + 64;
    const uint32_t PhU = base + OFF_PH;

    const int tid = threadIdx.x, lane = tid & 31, wid = tid >> 5;
    const int wm = wid & 1, wn = wid >> 1;
    const int q0 = blockIdx.x << 6;
    const int b  = blockIdx.y >> 4, h = blockIdx.y & 15;

    const __half* qb = qkv + (size_t)b * S_ * (3 * E_) + h * HD_;
    const __half* kb = qb + E_;
    const __half* vb = qb + 2 * E_;

    // Q tile (cp.async, one commit shared with first K/V stage)
    #pragma unroll
    for (int i = 0; i < 2; i++) {
        int idx = tid + (i << 8);
        int r = idx >> 3, c = idx & 7;
        cpa16(QsU + (uint32_t)(r * 144 + c * 16), qb + (size_t)(q0 + r) * (3 * E_) + c * 8);
    }
    if (tid < 64) { mrow[tid] = -1e30f; lrow[tid] = 0.f; }

    auto load_kv = [&](int t, int s) {
        #pragma unroll
        for (int i = 0; i < 2; i++) {
            int idx = tid + (i << 8);
            int r = idx >> 3, c = idx & 7;
            size_t go = (size_t)(t * 64 + r) * (3 * E_) + c * 8;
            cpa16(KsU + (uint32_t)(s * 9216 + r * 144 + c * 16), kb + go);
            cpa16(VsU + (uint32_t)(s * 9216 + r * 144 + c * 16), vb + go);
        }
    };
    load_kv(0, 0);
    CP_COMMIT();

    const uint32_t a_lane = (uint32_t)((lane & 15) * 144 + (lane >> 4) * 16);
    const int rh = lane >> 2, c2 = (lane & 3) * 2;
    // K (non-trans) lane map: key row + d chunk
    const int kKey = ((lane >> 4) & 1) * 8 + (lane & 7);
    const int kDb  = ((lane >> 3) & 1) * 16;            // d byte offset within 32B
    // V (trans) lane map
    const int vKey = ((lane >> 3) & 1) * 8 + (lane & 7);
    const int vD   = ((lane >> 4) & 1) * 8;

    float O[2][2][4];
    #pragma unroll
    for (int a = 0; a < 2; a++)
        #pragma unroll
        for (int bb = 0; bb < 2; bb++)
            #pragma unroll
            for (int q = 0; q < 4; q++) O[a][bb][q] = 0.f;

    for (int t = 0; t < S_ / 64; ++t) {
        const int s = t & 1;
        CP_WAIT0();
        __syncthreads();
        if (t + 1 < S_ / 64) { load_kv(t + 1, s ^ 1); CP_COMMIT(); }

        // ---- S = Q K^T ----
        float sf[2][2][4];
        #pragma unroll
        for (int a = 0; a < 2; a++)
            #pragma unroll
            for (int bb = 0; bb < 2; bb++)
                #pragma unroll
                for (int q = 0; q < 4; q++) sf[a][bb][q] = 0.f;

        #pragma unroll
        for (int kk = 0; kk < 4; kk++) {
            uint32_t af[2][4];
            #pragma unroll
            for (int mt = 0; mt < 2; mt++)
                ldsm4(af[mt][0], af[mt][1], af[mt][2], af[mt][3],
                      QsU + (uint32_t)((wm * 32 + mt * 16) * 144 + kk * 32) + a_lane);
            uint32_t r0, r1, r2, r3;
            uint32_t kaddr = KsU + (uint32_t)(s * 9216 + (wn * 16 + kKey) * 144
                             + kk * 32 + kDb);
            ldsm4(r0, r1, r2, r3, kaddr);
            uint32_t bf[2][2] = {{r0, r1}, {r2, r3}};
            #pragma unroll
            for (int mt = 0; mt < 2; mt++)
                #pragma unroll
                for (int nt = 0; nt < 2; nt++)
                    mma_f16(sf[mt][nt], af[mt], bf[nt]);
        }
        // scaled S -> Sf (fp32)
        #pragma unroll
        for (int mt = 0; mt < 2; mt++)
            #pragma unroll
            for (int nt = 0; nt < 2; nt++) {
                int row0 = wm * 32 + mt * 16 + rh;
                int col  = wn * 16 + nt * 8 + c2;
                *(float2*)&Sf[row0 * 68 + col] =
                    make_float2(sf[mt][nt][0] * 0.125f, sf[mt][nt][1] * 0.125f);
                *(float2*)&Sf[(row0 + 8) * 68 + col] =
                    make_float2(sf[mt][nt][2] * 0.125f, sf[mt][nt][3] * 0.125f);
            }
        __syncthreads();

        // ---- online softmax: 4 threads/row; write P fp16 ----
        {
            int row = tid >> 2;
            float* sr = Sf + row * 68 + (tid & 3) * 16;
            float4 v0 = *(float4*)(sr),     v1 = *(float4*)(sr + 4),
                   v2 = *(float4*)(sr + 8), v3 = *(float4*)(sr + 12);
            float mx = fmaxf(fmaxf(fmaxf(v0.x, v0.y), fmaxf(v0.z, v0.w)),
                             fmaxf(fmaxf(v1.x, v1.y), fmaxf(v1.z, v1.w)));
            mx = fmaxf(mx, fmaxf(fmaxf(fmaxf(v2.x, v2.y), fmaxf(v2.z, v2.w)),
                                 fmaxf(fmaxf(v3.x, v3.y), fmaxf(v3.z, v3.w))));
            mx = fmaxf(mx, __shfl_xor_sync(0xffffffffu, mx, 1));
            mx = fmaxf(mx, __shfl_xor_sync(0xffffffffu, mx, 2));
            float mo = mrow[row];
            float mn = fmaxf(mo, mx);
            v0.x = __expf(v0.x - mn); v0.y = __expf(v0.y - mn);
            v0.z = __expf(v0.z - mn); v0.w = __expf(v0.w - mn);
            v1.x = __expf(v1.x - mn); v1.y = __expf(v1.y - mn);
            v1.z = __expf(v1.z - mn); v1.w = __expf(v1.w - mn);
            v2.x = __expf(v2.x - mn); v2.y = __expf(v2.y - mn);
            v2.z = __expf(v2.z - mn); v2.w = __expf(v2.w - mn);
            v3.x = __expf(v3.x - mn); v3.y = __expf(v3.y - mn);
            v3.z = __expf(v3.z - mn); v3.w = __expf(v3.w - mn);
            __half2 hp[8];
            hp[0] = __floats2half2_rn(v0.x, v0.y); hp[1] = __floats2half2_rn(v0.z, v0.w);
            hp[2] = __floats2half2_rn(v1.x, v1.y); hp[3] = __floats2half2_rn(v1.z, v1.w);
            hp[4] = __floats2half2_rn(v2.x, v2.y); hp[5] = __floats2half2_rn(v2.z, v2.w);
            hp[6] = __floats2half2_rn(v3.x, v3.y); hp[7] = __floats2half2_rn(v3.z, v3.w);
            uint4* pdst = (uint4*)(Ph + row * 72 + (tid & 3) * 16);
            pdst[0] = *(uint4*)&hp[0];
            pdst[1] = *(uint4*)&hp[4];
            float su = v0.x + v0.y + v0.z + v0.w + v1.x + v1.y + v1.z + v1.w
                     + v2.x + v2.y + v2.z + v2.w + v3.x + v3.y + v3.z + v3.w;
            su += __shfl_xor_sync(0xffffffffu, su, 1);
            su += __shfl_xor_sync(0xffffffffu, su, 2);
            if ((tid & 3) == 0) {
                float al = __expf(mo - mn);
                arow[row] = al;
                lrow[row] = lrow[row] * al + su;
                mrow[row] = mn;
            }
        }
        __syncthreads();

        // ---- rescale O; O += P @ V ----
        #pragma unroll
        for (int mt = 0; mt < 2; mt++) {
            float a0 = arow[wm * 32 + mt * 16 + rh];
            float a1 = arow[wm * 32 + mt * 16 + 8 + rh];
            #pragma unroll
            for (int nt = 0; nt < 2; nt++) {
                O[mt][nt][0] *= a0; O[mt][nt][1] *= a0;
                O[mt][nt][2] *= a1; O[mt][nt][3] *= a1;
            }
        }
        #pragma unroll
        for (int kk = 0; kk < 4; kk++) {
            uint32_t af[2][4];
            #pragma unroll
            for (int mt = 0; mt < 2; mt++)
                ldsm4(af[mt][0], af[mt][1], af[mt][2], af[mt][3],
                      PhU + (uint32_t)((wm * 32 + mt * 16) * 144 + kk * 32) + a_lane);
            uint32_t r0, r1, r2, r3;
            uint32_t vaddr = VsU + (uint32_t)(s * 9216 + (kk * 16 + vKey) * 144
                             + (wn * 16 + vD) * 2);
            ldsm4t(r0, r1, r2, r3, vaddr);
            uint32_t bf[2][2] = {{r0, r1}, {r2, r3}};
            #pragma unroll
            for (int mt = 0; mt < 2; mt++)
                #pragma unroll
                for (int nt = 0; nt < 2; nt++)
                    mma_f16(O[mt][nt], af[mt], bf[nt]);
        }
    }

    // ---- normalize + write fp16 ----
    #pragma unroll
    for (int mt = 0; mt < 2; mt++) {
        int row0 = wm * 32 + mt * 16 + rh;
        float inv0 = 1.f / lrow[row0];
        float inv1 = 1.f / lrow[row0 + 8];
        #pragma unroll
        for (int nt = 0; nt < 2; nt++) {
            int col = h * HD_ + wn * 16 + nt * 8 + c2;
            *(__half2*)&attn[(size_t)(b * S_ + q0 + row0) * E_ + col] =
                __floats2half2_rn(O[mt][nt][0] * inv0, O[mt][nt][1] * inv0);
            *(__half2*)&attn[(size_t)(b * S_ + q0 + row0 + 8) * E_ + col] =
                __floats2half2_rn(O[mt][nt][2] * inv1, O[mt][nt][3] * inv1);
        }
    }
}

// ---------------------------------------------------------------------------
// Fused residual-add + LayerNorm; optional fp16 secondary output.
// ---------------------------------------------------------------------------
template<int WH>
__global__ void __launch_bounds__(256) ln_kernel(
    const float* __restrict__ a, const float* __restrict__ bsrc,
    const float* __restrict__ g, const float* __restrict__ be,
    float* __restrict__ out, __half* __restrict__ outh)
{
    const int tok = blockIdx.x;
    const int tid = threadIdx.x;
    const float* pa = a    + (size_t)tok * E_;
    const float* pb = bsrc + (size_t)tok * E_;

    float r[4]; float s = 0.f;
    #pragma unroll
    for (int i = 0; i < 4; i++) {
        int e = tid + (i << 8);
        r[i] = pa[e] + pb[e];
        s += r[i];
    }
    __shared__ float red[8];
    #pragma unroll
    for (int o = 16; o > 0; o >>= 1) s += __shfl_xor_sync(0xffffffffu, s, o);
    if ((tid & 31) == 0) red[tid >> 5] = s;
    __syncthreads();
    float tot = 0.f;
    #pragma unroll
    for (int w = 0; w < 8; w++) tot += red[w];
    const float mean = tot * (1.0f / E_);

    float vs = 0.f;
    #pragma unroll
    for (int i = 0; i < 4; i++) { float d = r[i] - mean; vs += d * d; }
    #pragma unroll
    for (int o = 16; o > 0; o >>= 1) vs += __shfl_xor_sync(0xffffffffu, vs, o);
    __syncthreads();
    if ((tid & 31) == 0) red[tid >> 5] = vs;
    __syncthreads();
    float vtot = 0.f;
    #pragma unroll
    for (int w = 0; w < 8; w++) vtot += red[w];
    const float rstd = rsqrtf(vtot * (1.0f / E_) + 1e-5f);

    #pragma unroll
    for (int i = 0; i < 4; i++) {
        int e = tid + (i << 8);
        float v = (r[i] - mean) * rstd * g[e] + be[e];
        out[(size_t)tok * E_ + e] = v;
        if (WH) outh[(size_t)tok * E_ + e] = __float2half(v);
    }
}

// ---------------------------------------------------------------------------
extern "C" void kernel_launch(void* const* d_in, const int* in_sizes, int n_in,
                              void* d_out, int out_size)
{
    const float* x     = (const float*)d_in[0];
    const float* w_qkv = (const float*)d_in[1];
    const float* b_qkv = (const float*)d_in[2];
    const float* w_out = (const float*)d_in[3];
    const float* b_out = (const float*)d_in[4];
    const float* w_ff1 = (const float*)d_in[5];
    const float* b_ff1 = (const float*)d_in[6];
    const float* w_ff2 = (const float*)d_in[7];
    const float* b_ff2 = (const float*)d_in[8];
    const float* g1    = (const float*)d_in[9];
    const float* be1   = (const float*)d_in[10];
    const float* g2    = (const float*)d_in[11];
    const float* be2   = (const float*)d_in[12];
    float* out = (float*)d_out;

    __half *p_hx, *p_wqkv, *p_wout, *p_wff1, *p_wff2;
    __half *p_qkv, *p_attn, *p_x1h, *p_ff1;
    float *p_proj, *p_x1f, *p_ff2;
    cudaGetSymbolAddress((void**)&p_hx,   h_x);
    cudaGetSymbolAddress((void**)&p_wqkv, h_wqkv);
    cudaGetSymbolAddress((void**)&p_wout, h_wout);
    cudaGetSymbolAddress((void**)&p_wff1, h_wff1);
    cudaGetSymbolAddress((void**)&p_wff2, h_wff2);
    cudaGetSymbolAddress((void**)&p_qkv,  h_qkv);
    cudaGetSymbolAddress((void**)&p_attn, h_attn);
    cudaGetSymbolAddress((void**)&p_x1h,  h_x1);
    cudaGetSymbolAddress((void**)&p_ff1,  h_ff1);
    cudaGetSymbolAddress((void**)&p_proj, s_proj);
    cudaGetSymbolAddress((void**)&p_x1f,  s_x1f);
    cudaGetSymbolAddress((void**)&p_ff2,  s_ff2);

    cudaFuncSetAttribute(gemm_h<0,1>, cudaFuncAttributeMaxDynamicSharedMemorySize, GEMM_SMEM);
    cudaFuncSetAttribute(gemm_h<0,0>, cudaFuncAttributeMaxDynamicSharedMemorySize, GEMM_SMEM);
    cudaFuncSetAttribute(gemm_h<1,1>, cudaFuncAttributeMaxDynamicSharedMemorySize, GEMM_SMEM);
    cudaFuncSetAttribute(flash_h,     cudaFuncAttributeMaxDynamicSharedMemorySize, FLASH_SMEM);

    // 0) fp32 -> fp16 conversions
    conv_h<<<(M_*E_)/1024, 256>>>((const float4*)x, (__half2*)p_hx);
    conv_h<<<(E_*3*E_)/1024, 256>>>((const float4*)w_qkv, (__half2*)p_wqkv);
    conv_h<<<(E_*E_)/1024, 256>>>((const float4*)w_out, (__half2*)p_wout);
    conv_h<<<(E_*FF_)/1024, 256>>>((const float4*)w_ff1, (__half2*)p_wff1);
    conv_h<<<(FF_*E_)/1024, 256>>>((const float4*)w_ff2, (__half2*)p_wff2);

    // 1) QKV projection (fp16 out)
    gemm_h<0,1><<<dim3(3 * E_ / 128, M_ / 128), 256, GEMM_SMEM>>>(
        p_hx, p_wqkv, b_qkv, p_qkv, M_, 3 * E_, E_);

    // 2) flash attention (fp16)
    flash_h<<<dim3(S_ / 64, B_ * H_), 256, FLASH_SMEM>>>(p_qkv, p_attn);

    // 3) output projection (fp32 out)
    gemm_h<0,0><<<dim3(E_ / 128, M_ / 128), 256, GEMM_SMEM>>>(
        p_attn, p_wout, b_out, p_proj, M_, E_, E_);

    // 4) LN1 (fp32 + fp16 out)
    ln_kernel<1><<<M_, 256>>>(x, p_proj, g1, be1, p_x1f, p_x1h);

    // 5) FF1 + GELU (fp16 out)
    gemm_h<1,1><<<dim3(FF_ / 128, M_ / 128), 256, GEMM_SMEM>>>(
        p_x1h, p_wff1, b_ff1, p_ff1, M_, FF_, E_);

    // 6) FF2 (fp32 out)
    gemm_h<0,0><<<dim3(E_ / 128, M_ / 128), 256, GEMM_SMEM>>>(
        p_ff1, p_wff2, b_ff2, p_ff2, M_, E_, FF_);

    // 7) LN2 -> output
    ln_kernel<0><<<M_, 256>>>(p_x1f, p_ff2, g2, be2, out, nullptr);
}